// round 8
// baseline (speedup 1.0000x reference)
#include <cuda_runtime.h>
#include <cstdint>
#include <math.h>

// ---------------- problem constants -----------------------------------------
#define N_TOK 16384
#define H_DIM 1024
#define E_NUM 8
#define E_DIM 512
#define VOCAB 50257
#define PADMAX (N_TOK + E_NUM * 128)   // 17408

// ---------------- device state & scratch -------------------------------------
__device__ int d_counts[E_NUM];
__device__ int d_cursor[E_NUM];
__device__ int d_poff[E_NUM + 1];
__device__ int d_padded_total;
__device__ int d_perm[PADMAX];

__device__ float g_Xs [(size_t)N_TOK * 1024];    // tf32-rounded x
__device__ float g_Hs [(size_t)N_TOK * 1024];    // shared hidden (rounded)
__device__ float g_Hr [(size_t)PADMAX * 512];    // routed hidden (rounded)
__device__ float g_sgT[(size_t)1024 * 1024];
__device__ float g_suT[(size_t)1024 * 1024];
__device__ float g_sdT[(size_t)1024 * 1024];
__device__ float g_gT [(size_t)E_NUM * 512 * 1024];
__device__ float g_uT [(size_t)E_NUM * 512 * 1024];
__device__ float g_dT [(size_t)E_NUM * 1024 * 512];

// ---------------- helpers -----------------------------------------------------
__device__ __forceinline__ float tf32r(float x) {
    uint32_t u;
    asm("cvt.rna.tf32.f32 %0, %1;" : "=r"(u) : "f"(x));
    return __uint_as_float(u);
}
__device__ __forceinline__ uint32_t smem_u32(const void* p) {
    uint32_t a;
    asm("{ .reg .u64 t; cvta.to.shared.u64 t, %1; cvt.u32.u64 %0, t; }" : "=r"(a) : "l"(p));
    return a;
}
#define CP_ASYNC16(dst, src) \
    asm volatile("cp.async.cg.shared.global [%0], [%1], 16;" :: "r"(dst), "l"(src))
#define CP_ASYNC16Z(dst, src, sz) \
    asm volatile("cp.async.cg.shared.global [%0], [%1], 16, %2;" :: "r"(dst), "l"(src), "r"(sz))
#define CP_COMMIT() asm volatile("cp.async.commit_group;")
#define CP_WAIT1()  asm volatile("cp.async.wait_group 1;")

#define LDSM4(r, addr) \
    asm volatile("ldmatrix.sync.aligned.m8n8.x4.shared.b16 {%0,%1,%2,%3}, [%4];" \
        : "=r"((r)[0]), "=r"((r)[1]), "=r"((r)[2]), "=r"((r)[3]) : "r"(addr))

__device__ __forceinline__ void mma8(float* d, const uint32_t* a, uint32_t b0, uint32_t b1) {
    asm volatile("mma.sync.aligned.m16n8k8.row.col.f32.tf32.tf32.f32 "
        "{%0,%1,%2,%3}, {%4,%5,%6,%7}, {%8,%9}, {%0,%1,%2,%3};"
        : "+f"(d[0]), "+f"(d[1]), "+f"(d[2]), "+f"(d[3])
        : "r"(a[0]), "r"(a[1]), "r"(a[2]), "r"(a[3]), "r"(b0), "r"(b1));
}
__device__ __forceinline__ float silu_f(float g) { return g / (1.f + __expf(-g)); }

// ---------------- routing -----------------------------------------------------
__global__ void k_init() {
    int i = blockIdx.x * blockDim.x + threadIdx.x;
    if (i < E_NUM) { d_counts[i] = 0; d_cursor[i] = 0; }
    for (int j = i; j < PADMAX; j += gridDim.x * blockDim.x) d_perm[j] = -1;
}
__device__ __forceinline__ int expert_of(int t) {
    t = t < 0 ? 0 : (t > VOCAB - 1 ? VOCAB - 1 : t);
    return t & (E_NUM - 1);
}
__global__ void k_hist(const int* __restrict__ tok) {
    int i = blockIdx.x * blockDim.x + threadIdx.x;
    if (i < N_TOK) atomicAdd(&d_counts[expert_of(tok[i])], 1);
}
__global__ void k_scan() {
    if (threadIdx.x == 0) {
        int acc = 0; d_poff[0] = 0;
        for (int e = 0; e < E_NUM; e++) { acc += (d_counts[e] + 127) & ~127; d_poff[e + 1] = acc; }
        d_padded_total = acc;
    }
}
__global__ void k_scatter(const int* __restrict__ tok) {
    int i = blockIdx.x * blockDim.x + threadIdx.x;
    if (i < N_TOK) {
        int e = expert_of(tok[i]);
        int p = atomicAdd(&d_cursor[e], 1);
        d_perm[d_poff[e] + p] = i;
    }
}

// ---------------- transposes (tf32-rounding) ----------------------------------
#define TR_BODY(ip, op, R, C) do { \
    __shared__ float tile[32][33]; \
    int r0 = blockIdx.y * 32, c0 = blockIdx.x * 32; \
    int tx = threadIdx.x, ty = threadIdx.y; \
    _Pragma("unroll") \
    for (int i = 0; i < 32; i += 8) tile[ty + i][tx] = (ip)[(size_t)(r0 + ty + i) * (C) + c0 + tx]; \
    __syncthreads(); \
    _Pragma("unroll") \
    for (int i = 0; i < 32; i += 8) (op)[(size_t)(c0 + ty + i) * (R) + r0 + tx] = tf32r(tile[tx][ty + i]); \
} while (0)

__global__ void k_tr_shared(const float* __restrict__ sg, const float* __restrict__ su,
                            const float* __restrict__ sd) {
    int z = blockIdx.z;
    const float* ip = z == 0 ? sg : (z == 1 ? su : sd);
    float* op = z == 0 ? g_sgT : (z == 1 ? g_suT : g_sdT);
    TR_BODY(ip, op, 1024, 1024);
}
__global__ void k_tr_gu(const float* __restrict__ gw, const float* __restrict__ uw) {
    int z = blockIdx.z;                     // 0..15
    int e = z & 7;
    const float* ip = (z < 8 ? gw : uw) + (size_t)e * 1024 * 512;
    float* op = (z < 8 ? g_gT : g_uT) + (size_t)e * 512 * 1024;
    TR_BODY(ip, op, 1024, 512);
}
__global__ void k_tr_down(const float* __restrict__ dw) {
    int e = blockIdx.z;                     // 0..7
    const float* ip = dw + (size_t)e * 512 * 1024;
    float* op = g_dT + (size_t)e * 1024 * 512;
    TR_BODY(ip, op, 512, 1024);
}

__global__ void k_round(const float* __restrict__ in, float* __restrict__ out) {
    size_t i = (size_t)blockIdx.x * blockDim.x + threadIdx.x;   // N_TOK*256 float4
    float4 v = reinterpret_cast<const float4*>(in)[i];
    reinterpret_cast<float4*>(out)[i] =
        make_float4(tf32r(v.x), tf32r(v.y), tf32r(v.z), tf32r(v.w));
}

// ---------------- fused tf32 mma.sync GEMM ------------------------------------
// Modes:
//  F_SWIGLU: B-smem rows interleave gate(even)/up(odd); CTA covers 64 true cols;
//            epilogue writes tf32r(silu(g)*u).
//  F_AMAP:   A rows gathered via d_perm (pads zero-filled).
//  F_SCATTER: epilogue does out[d_perm[r]] += acc (plain-N mode only).
#define BKG 32
#define RSF 144                     // smem row stride bytes
#define STG_B (128 * RSF)           // 18432 bytes per operand per stage
#define NST 3
#define GEMM_SMEM (NST * STG_B * 2)
#define F_EXPERT  1
#define F_LIMIT   2
#define F_AMAP    4
#define F_SWIGLU  8
#define F_SCATTER 16

__global__ __launch_bounds__(256)
void k_mma(const float* __restrict__ A, const float* __restrict__ Bg,
           const float* __restrict__ Bu, float* __restrict__ C,
           int K, long long ew_stride, int ldc, int flags)
{
    extern __shared__ __align__(128) float sm[];
    __shared__ int s_map[128];
    int row0 = blockIdx.y * 128;
    if ((flags & F_LIMIT) && row0 >= d_padded_total) return;
    int tid = threadIdx.x;

    if (tid < 128) {
        int gr = row0 + tid;
        s_map[tid] = (flags & F_AMAP) ? d_perm[gr] : gr;
    }

    const float* bg = Bg; const float* bu = Bu;
    if (flags & F_EXPERT) {
        int e = 0;
        #pragma unroll
        for (int i = 1; i < E_NUM; i++) if (row0 >= d_poff[i]) e = i;
        bg += (long long)e * ew_stride;
        bu += (long long)e * ew_stride;
    }
    const bool sw = (flags & F_SWIGLU) != 0;
    int col0 = blockIdx.x * (sw ? 64 : 128);

    uint32_t sA = smem_u32(sm);
    uint32_t sB = sA + NST * STG_B;

    int lane = tid & 31, wid = tid >> 5;
    int wm = wid >> 1, wn = wid & 1;            // 4 x 2 warps
    int tq = lane & 7, sel = lane >> 3;

    uint32_t aoff[2], boff[4];
    #pragma unroll
    for (int fm = 0; fm < 2; fm++)
        aoff[fm] = (uint32_t)((wm * 32 + fm * 16 + tq + (sel & 1) * 8) * RSF + ((sel >> 1) * 4) * 4);
    #pragma unroll
    for (int p = 0; p < 4; p++)
        boff[p] = (uint32_t)((wn * 64 + p * 16 + tq + (sel >> 1) * 8) * RSF + ((sel & 1) * 4) * 4);

    __syncthreads();   // s_map ready

    auto load_stage = [&](int st, int kt) {
        uint32_t da = sA + st * STG_B, db = sB + st * STG_B;
        int kof = kt * BKG;
        #pragma unroll
        for (int p = 0; p < 4; p++) {
            int g = p * 256 + tid;
            int r = g >> 3, c = g & 7;
            int ar = s_map[r];
            const float* asrc = A + ((size_t)(ar < 0 ? 0 : ar) * K + kof + c * 4);
            uint32_t asz = ar < 0 ? 0u : 16u;
            CP_ASYNC16Z(da + (uint32_t)(r * RSF + c * 16), asrc, asz);
            const float* bsrc;
            if (sw) {
                const float* bb = (r & 1) ? bu : bg;
                bsrc = bb + ((size_t)(col0 + (r >> 1)) * K + kof + c * 4);
            } else {
                bsrc = bg + ((size_t)(col0 + r) * K + kof + c * 4);
            }
            CP_ASYNC16(db + (uint32_t)(r * RSF + c * 16), bsrc);
        }
    };

    int KT = K / BKG;
    load_stage(0, 0); CP_COMMIT();
    load_stage(1, 1); CP_COMMIT();
    CP_WAIT1();
    __syncthreads();

    float acc[2][8][4];
    #pragma unroll
    for (int fm = 0; fm < 2; fm++)
        #pragma unroll
        for (int fn = 0; fn < 8; fn++)
            #pragma unroll
            for (int q = 0; q < 4; q++) acc[fm][fn][q] = 0.f;

    for (int kt = 0; kt < KT; kt++) {
        int st = kt % NST;
        uint32_t baseA = sA + st * STG_B, baseB = sB + st * STG_B;
        #pragma unroll
        for (int s = 0; s < 4; s++) {
            uint32_t a[2][4], b[4][4];
            #pragma unroll
            for (int fm = 0; fm < 2; fm++) LDSM4(a[fm], baseA + aoff[fm] + s * 32);
            #pragma unroll
            for (int p = 0; p < 4; p++)  LDSM4(b[p], baseB + boff[p] + s * 32);
            #pragma unroll
            for (int fm = 0; fm < 2; fm++)
                #pragma unroll
                for (int fn = 0; fn < 8; fn++) {
                    const uint32_t* bp = b[fn >> 1];
                    if (fn & 1) mma8(acc[fm][fn], a[fm], bp[2], bp[3]);
                    else        mma8(acc[fm][fn], a[fm], bp[0], bp[1]);
                }
        }
        if (kt + 2 < KT) load_stage((kt + 2) % NST, kt + 2);
        CP_COMMIT();
        CP_WAIT1();
        __syncthreads();
    }

    int gid = lane >> 2, tig = lane & 3;
    if (sw) {
        // acc pair (2*tig, 2*tig+1) in B-space = (gate, up) of true col tc
        #pragma unroll
        for (int fm = 0; fm < 2; fm++) {
            int r = row0 + wm * 32 + fm * 16 + gid;
            #pragma unroll
            for (int fn = 0; fn < 8; fn++) {
                int tc = col0 + wn * 32 + fn * 4 + tig;
                float* d = acc[fm][fn];
                C[(size_t)r * ldc + tc]       = tf32r(silu_f(d[0]) * d[1]);
                C[(size_t)(r + 8) * ldc + tc] = tf32r(silu_f(d[2]) * d[3]);
            }
        }
    } else if (flags & F_SCATTER) {
        #pragma unroll
        for (int fm = 0; fm < 2; fm++) {
            #pragma unroll
            for (int q = 0; q < 2; q++) {
                int r = row0 + wm * 32 + fm * 16 + gid + q * 8;
                int t = d_perm[r];
                if (t < 0) continue;
                #pragma unroll
                for (int fn = 0; fn < 8; fn++) {
                    int c = col0 + wn * 64 + fn * 8 + 2 * tig;
                    float2* p = reinterpret_cast<float2*>(&C[(size_t)t * ldc + c]);
                    float2 v = *p;
                    v.x += acc[fm][fn][q * 2];
                    v.y += acc[fm][fn][q * 2 + 1];
                    *p = v;
                }
            }
        }
    } else {
        #pragma unroll
        for (int fm = 0; fm < 2; fm++) {
            #pragma unroll
            for (int fn = 0; fn < 8; fn++) {
                int r = row0 + wm * 32 + fm * 16 + gid;
                int c = col0 + wn * 64 + fn * 8 + 2 * tig;
                *reinterpret_cast<float2*>(&C[(size_t)r * ldc + c]) =
                    make_float2(acc[fm][fn][0], acc[fm][fn][1]);
                *reinterpret_cast<float2*>(&C[(size_t)(r + 8) * ldc + c]) =
                    make_float2(acc[fm][fn][2], acc[fm][fn][3]);
            }
        }
    }
}

// ---------------- launch ------------------------------------------------------
extern "C" void kernel_launch(void* const* d_in, const int* in_sizes, int n_in,
                              void* d_out, int out_size) {
    const float* x      = (const float*)d_in[0];
    const int*   tok    = (const int*)  d_in[1];
    const float* gate_w = (const float*)d_in[2];
    const float* up_w   = (const float*)d_in[3];
    const float* down_w = (const float*)d_in[4];
    const float* sg     = (const float*)d_in[5];
    const float* su     = (const float*)d_in[6];
    const float* sd     = (const float*)d_in[7];
    float* out = (float*)d_out;

    float *Xs, *Hs, *Hr, *sgT, *suT, *sdT, *gT, *uT, *dT;
    cudaGetSymbolAddress((void**)&Xs, g_Xs);
    cudaGetSymbolAddress((void**)&Hs, g_Hs);
    cudaGetSymbolAddress((void**)&Hr, g_Hr);
    cudaGetSymbolAddress((void**)&sgT, g_sgT);
    cudaGetSymbolAddress((void**)&suT, g_suT);
    cudaGetSymbolAddress((void**)&sdT, g_sdT);
    cudaGetSymbolAddress((void**)&gT, g_gT);
    cudaGetSymbolAddress((void**)&uT, g_uT);
    cudaGetSymbolAddress((void**)&dT, g_dT);

    cudaFuncSetAttribute(k_mma, cudaFuncAttributeMaxDynamicSharedMemorySize, GEMM_SMEM);

    // routing
    k_init   <<<(PADMAX + 255) / 256, 256>>>();
    k_hist   <<<(N_TOK + 255) / 256, 256>>>(tok);
    k_scan   <<<1, 32>>>();
    k_scatter<<<(N_TOK + 255) / 256, 256>>>(tok);

    // weight transposes ([K,N] -> [N,K]) with tf32 rounding
    dim3 tb(32, 8);
    k_tr_shared<<<dim3(32, 32, 3), tb>>>(sg, su, sd);
    k_tr_gu    <<<dim3(16, 32, 16), tb>>>(gate_w, up_w);
    k_tr_down  <<<dim3(32, 16, 8), tb>>>(down_w);

    // round activations once
    k_round<<<N_TOK, 256>>>(x, Xs);

    // shared up + swiglu fused: Hs[N,1024]
    k_mma<<<dim3(16, 128), 256, GEMM_SMEM>>>(Xs, sgT, suT, Hs,
        1024, 0LL, 1024, F_SWIGLU);

    // routed up + gather + swiglu fused: Hr[pad,512]
    k_mma<<<dim3(8, PADMAX / 128), 256, GEMM_SMEM>>>(Xs, gT, uT, Hr,
        1024, (long long)512 * 1024, 512, F_SWIGLU | F_AMAP | F_EXPERT | F_LIMIT);

    // shared down: out = Hs @ sdT^T (full overwrite)
    k_mma<<<dim3(8, 128), 256, GEMM_SMEM>>>(Hs, sdT, sdT, out,
        1024, 0LL, 1024, 0);

    // routed down + scatter-add fused: out[perm[r]] += Hr @ dT[e]^T
    k_mma<<<dim3(8, PADMAX / 128), 256, GEMM_SMEM>>>(Hr, dT, dT, out,
        512, (long long)1024 * 512, 1024, F_EXPERT | F_LIMIT | F_SCATTER);
}

// round 9
// speedup vs baseline: 1.3066x; 1.3066x over previous
#include <cuda_runtime.h>
#include <cstdint>
#include <math.h>

// ---------------- problem constants -----------------------------------------
#define N_TOK 16384
#define H_DIM 1024
#define E_NUM 8
#define E_DIM 512
#define VOCAB 50257
#define PADMAX (N_TOK + E_NUM * 128)   // 17408

// ---------------- device state & scratch -------------------------------------
__device__ int d_counts[E_NUM];
__device__ int d_cursor[E_NUM];
__device__ int d_poff[E_NUM + 1];
__device__ int d_padded_total;
__device__ int d_perm[PADMAX];

__device__ float g_Xs [(size_t)N_TOK * 1024];    // tf32-rounded x
__device__ float g_Hs [(size_t)N_TOK * 1024];    // shared hidden (rounded)
__device__ float g_Hr [(size_t)PADMAX * 512];    // routed hidden (rounded)
__device__ float g_sgT[(size_t)1024 * 1024];
__device__ float g_suT[(size_t)1024 * 1024];
__device__ float g_sdT[(size_t)1024 * 1024];
__device__ float g_gT [(size_t)E_NUM * 512 * 1024];
__device__ float g_uT [(size_t)E_NUM * 512 * 1024];
__device__ float g_dT [(size_t)E_NUM * 1024 * 512];

// ---------------- helpers -----------------------------------------------------
__device__ __forceinline__ float tf32r(float x) {
    uint32_t u;
    asm("cvt.rna.tf32.f32 %0, %1;" : "=r"(u) : "f"(x));
    return __uint_as_float(u);
}
__device__ __forceinline__ uint32_t smem_u32(const void* p) {
    uint32_t a;
    asm("{ .reg .u64 t; cvta.to.shared.u64 t, %1; cvt.u32.u64 %0, t; }" : "=r"(a) : "l"(p));
    return a;
}
#define CP_ASYNC16(dst, src) \
    asm volatile("cp.async.cg.shared.global [%0], [%1], 16;" :: "r"(dst), "l"(src))
#define CP_ASYNC16Z(dst, src, sz) \
    asm volatile("cp.async.cg.shared.global [%0], [%1], 16, %2;" :: "r"(dst), "l"(src), "r"(sz))
#define CP_COMMIT() asm volatile("cp.async.commit_group;")
#define CP_WAIT1()  asm volatile("cp.async.wait_group 1;")

#define LDSM4(r, addr) \
    asm volatile("ldmatrix.sync.aligned.m8n8.x4.shared.b16 {%0,%1,%2,%3}, [%4];" \
        : "=r"((r)[0]), "=r"((r)[1]), "=r"((r)[2]), "=r"((r)[3]) : "r"(addr))

__device__ __forceinline__ void mma8(float* d, const uint32_t* a, uint32_t b0, uint32_t b1) {
    asm volatile("mma.sync.aligned.m16n8k8.row.col.f32.tf32.tf32.f32 "
        "{%0,%1,%2,%3}, {%4,%5,%6,%7}, {%8,%9}, {%0,%1,%2,%3};"
        : "+f"(d[0]), "+f"(d[1]), "+f"(d[2]), "+f"(d[3])
        : "r"(a[0]), "r"(a[1]), "r"(a[2]), "r"(a[3]), "r"(b0), "r"(b1));
}
__device__ __forceinline__ float silu_f(float g) { return g / (1.f + __expf(-g)); }

// ---------------- routing -----------------------------------------------------
__global__ void k_init() {
    int i = blockIdx.x * blockDim.x + threadIdx.x;
    if (i < E_NUM) { d_counts[i] = 0; d_cursor[i] = 0; }
    for (int j = i; j < PADMAX; j += gridDim.x * blockDim.x) d_perm[j] = -1;
}
__device__ __forceinline__ int expert_of(int t) {
    t = t < 0 ? 0 : (t > VOCAB - 1 ? VOCAB - 1 : t);
    return t & (E_NUM - 1);
}
__global__ void k_hist(const int* __restrict__ tok) {
    int i = blockIdx.x * blockDim.x + threadIdx.x;
    if (i < N_TOK) atomicAdd(&d_counts[expert_of(tok[i])], 1);
}
__global__ void k_scan() {
    if (threadIdx.x == 0) {
        int acc = 0; d_poff[0] = 0;
        for (int e = 0; e < E_NUM; e++) { acc += (d_counts[e] + 127) & ~127; d_poff[e + 1] = acc; }
        d_padded_total = acc;
    }
}
__global__ void k_scatter(const int* __restrict__ tok) {
    int i = blockIdx.x * blockDim.x + threadIdx.x;
    if (i < N_TOK) {
        int e = expert_of(tok[i]);
        int p = atomicAdd(&d_cursor[e], 1);
        d_perm[d_poff[e] + p] = i;
    }
}

// ---------------- transposes (tf32-rounding) ----------------------------------
#define TR_BODY(ip, op, R, C) do { \
    __shared__ float tile[32][33]; \
    int r0 = blockIdx.y * 32, c0 = blockIdx.x * 32; \
    int tx = threadIdx.x, ty = threadIdx.y; \
    _Pragma("unroll") \
    for (int i = 0; i < 32; i += 8) tile[ty + i][tx] = (ip)[(size_t)(r0 + ty + i) * (C) + c0 + tx]; \
    __syncthreads(); \
    _Pragma("unroll") \
    for (int i = 0; i < 32; i += 8) (op)[(size_t)(c0 + ty + i) * (R) + r0 + tx] = tf32r(tile[tx][ty + i]); \
} while (0)

__global__ void k_tr_shared(const float* __restrict__ sg, const float* __restrict__ su,
                            const float* __restrict__ sd) {
    int z = blockIdx.z;
    const float* ip = z == 0 ? sg : (z == 1 ? su : sd);
    float* op = z == 0 ? g_sgT : (z == 1 ? g_suT : g_sdT);
    TR_BODY(ip, op, 1024, 1024);
}
__global__ void k_tr_gu(const float* __restrict__ gw, const float* __restrict__ uw) {
    int z = blockIdx.z;                     // 0..15
    int e = z & 7;
    const float* ip = (z < 8 ? gw : uw) + (size_t)e * 1024 * 512;
    float* op = (z < 8 ? g_gT : g_uT) + (size_t)e * 512 * 1024;
    TR_BODY(ip, op, 1024, 512);
}
__global__ void k_tr_down(const float* __restrict__ dw) {
    int e = blockIdx.z;                     // 0..7
    const float* ip = dw + (size_t)e * 512 * 1024;
    float* op = g_dT + (size_t)e * 1024 * 512;
    TR_BODY(ip, op, 512, 1024);
}

__global__ void k_round(const float* __restrict__ in, float* __restrict__ out) {
    size_t i = (size_t)blockIdx.x * blockDim.x + threadIdx.x;   // N_TOK*256 float4
    float4 v = reinterpret_cast<const float4*>(in)[i];
    reinterpret_cast<float4*>(out)[i] =
        make_float4(tf32r(v.x), tf32r(v.y), tf32r(v.z), tf32r(v.w));
}

// ---------------- fused tf32 mma.sync GEMM ------------------------------------
// Modes:
//  F_SWIGLU: B-smem rows interleave gate(even)/up(odd); CTA covers 64 true cols;
//            epilogue writes tf32r(silu(g)*u).
//  F_AMAP:   A rows gathered via d_perm (pads zero-filled) — resolved in
//            prologue to register base pointers; mainloop is pure ptr+kof.
//  F_SCATTER: epilogue does out[d_perm[r]] += acc (plain-N mode only).
#define BKG 32
#define RSF 144                     // smem row stride bytes
#define STG_B (128 * RSF)           // 18432 bytes per operand per stage
#define NST 3
#define GEMM_SMEM (NST * STG_B * 2)
#define F_EXPERT  1
#define F_LIMIT   2
#define F_AMAP    4
#define F_SWIGLU  8
#define F_SCATTER 16

__global__ __launch_bounds__(256)
void k_mma(const float* __restrict__ A, const float* __restrict__ Bg,
           const float* __restrict__ Bu, float* __restrict__ C,
           int K, long long ew_stride, int ldc, int flags)
{
    extern __shared__ __align__(128) float sm[];
    int row0 = blockIdx.y * 128;
    if ((flags & F_LIMIT) && row0 >= d_padded_total) return;
    int tid = threadIdx.x;

    const float* bg = Bg; const float* bu = Bu;
    if (flags & F_EXPERT) {
        int e = 0;
        #pragma unroll
        for (int i = 1; i < E_NUM; i++) if (row0 >= d_poff[i]) e = i;
        bg += (long long)e * ew_stride;
        bu += (long long)e * ew_stride;
    }
    const bool sw = (flags & F_SWIGLU) != 0;
    int col0 = blockIdx.x * (sw ? 64 : 128);

    uint32_t sA = smem_u32(sm);
    uint32_t sB = sA + NST * STG_B;

    int lane = tid & 31, wid = tid >> 5;
    int wm = wid >> 1, wn = wid & 1;            // 4 x 2 warps
    int tq = lane & 7, sel = lane >> 3;

    uint32_t aoff[2], boff[4];
    #pragma unroll
    for (int fm = 0; fm < 2; fm++)
        aoff[fm] = (uint32_t)((wm * 32 + fm * 16 + tq + (sel & 1) * 8) * RSF + ((sel >> 1) * 4) * 4);
    #pragma unroll
    for (int p = 0; p < 4; p++)
        boff[p] = (uint32_t)((wn * 64 + p * 16 + tq + (sel >> 1) * 8) * RSF + ((sel & 1) * 4) * 4);

    // ---- prologue: resolve per-thread load rows ONCE into registers ----------
    // Thread loads 4 (A,B) 16B chunks per stage at rows r(p) = (p*256+tid)>>3,
    // col chunk c(p) = (p*256+tid)&7 — constant across all k-iterations.
    const float* aP[4];
    const float* bP[4];
    uint32_t aSz[4], dOf[4];
    #pragma unroll
    for (int p = 0; p < 4; p++) {
        int g = p * 256 + tid;
        int r = g >> 3, c = g & 7;
        dOf[p] = (uint32_t)(r * RSF + c * 16);
        int gr = row0 + r;
        int ar = (flags & F_AMAP) ? d_perm[gr] : gr;
        aP[p]  = A + ((size_t)(ar < 0 ? 0 : ar) * K + c * 4);
        aSz[p] = ar < 0 ? 0u : 16u;
        if (sw) {
            const float* bb = (r & 1) ? bu : bg;
            bP[p] = bb + ((size_t)(col0 + (r >> 1)) * K + c * 4);
        } else {
            bP[p] = bg + ((size_t)(col0 + r) * K + c * 4);
        }
    }

    auto load_stage = [&](int st, int kt) {
        uint32_t da = sA + st * STG_B, db = sB + st * STG_B;
        int kof = kt * BKG;
        #pragma unroll
        for (int p = 0; p < 4; p++) {
            CP_ASYNC16Z(da + dOf[p], aP[p] + kof, aSz[p]);
            CP_ASYNC16 (db + dOf[p], bP[p] + kof);
        }
    };

    int KT = K / BKG;
    load_stage(0, 0); CP_COMMIT();
    load_stage(1, 1); CP_COMMIT();
    CP_WAIT1();
    __syncthreads();

    float acc[2][8][4];
    #pragma unroll
    for (int fm = 0; fm < 2; fm++)
        #pragma unroll
        for (int fn = 0; fn < 8; fn++)
            #pragma unroll
            for (int q = 0; q < 4; q++) acc[fm][fn][q] = 0.f;

    for (int kt = 0; kt < KT; kt++) {
        int st = kt % NST;
        uint32_t baseA = sA + st * STG_B, baseB = sB + st * STG_B;
        #pragma unroll
        for (int s = 0; s < 4; s++) {
            uint32_t a[2][4], b[4][4];
            #pragma unroll
            for (int fm = 0; fm < 2; fm++) LDSM4(a[fm], baseA + aoff[fm] + s * 32);
            #pragma unroll
            for (int p = 0; p < 4; p++)  LDSM4(b[p], baseB + boff[p] + s * 32);
            #pragma unroll
            for (int fm = 0; fm < 2; fm++)
                #pragma unroll
                for (int fn = 0; fn < 8; fn++) {
                    const uint32_t* bp = b[fn >> 1];
                    if (fn & 1) mma8(acc[fm][fn], a[fm], bp[2], bp[3]);
                    else        mma8(acc[fm][fn], a[fm], bp[0], bp[1]);
                }
        }
        if (kt + 2 < KT) load_stage((kt + 2) % NST, kt + 2);
        CP_COMMIT();
        CP_WAIT1();
        __syncthreads();
    }

    int gid = lane >> 2, tig = lane & 3;
    if (sw) {
        // acc pair layout: (even, odd) B-row = (gate, up) of true col tc
        #pragma unroll
        for (int fm = 0; fm < 2; fm++) {
            int r = row0 + wm * 32 + fm * 16 + gid;
            #pragma unroll
            for (int fn = 0; fn < 8; fn++) {
                int tc = col0 + wn * 32 + fn * 4 + tig;
                float* d = acc[fm][fn];
                C[(size_t)r * ldc + tc]       = tf32r(silu_f(d[0]) * d[1]);
                C[(size_t)(r + 8) * ldc + tc] = tf32r(silu_f(d[2]) * d[3]);
            }
        }
    } else if (flags & F_SCATTER) {
        #pragma unroll
        for (int fm = 0; fm < 2; fm++) {
            #pragma unroll
            for (int q = 0; q < 2; q++) {
                int r = row0 + wm * 32 + fm * 16 + gid + q * 8;
                int t = d_perm[r];
                if (t < 0) continue;
                #pragma unroll
                for (int fn = 0; fn < 8; fn++) {
                    int c = col0 + wn * 64 + fn * 8 + 2 * tig;
                    float2* p = reinterpret_cast<float2*>(&C[(size_t)t * ldc + c]);
                    float2 v = *p;
                    v.x += acc[fm][fn][q * 2];
                    v.y += acc[fm][fn][q * 2 + 1];
                    *p = v;
                }
            }
        }
    } else {
        #pragma unroll
        for (int fm = 0; fm < 2; fm++) {
            #pragma unroll
            for (int fn = 0; fn < 8; fn++) {
                int r = row0 + wm * 32 + fm * 16 + gid;
                int c = col0 + wn * 64 + fn * 8 + 2 * tig;
                *reinterpret_cast<float2*>(&C[(size_t)r * ldc + c]) =
                    make_float2(acc[fm][fn][0], acc[fm][fn][1]);
                *reinterpret_cast<float2*>(&C[(size_t)(r + 8) * ldc + c]) =
                    make_float2(acc[fm][fn][2], acc[fm][fn][3]);
            }
        }
    }
}

// ---------------- launch ------------------------------------------------------
extern "C" void kernel_launch(void* const* d_in, const int* in_sizes, int n_in,
                              void* d_out, int out_size) {
    const float* x      = (const float*)d_in[0];
    const int*   tok    = (const int*)  d_in[1];
    const float* gate_w = (const float*)d_in[2];
    const float* up_w   = (const float*)d_in[3];
    const float* down_w = (const float*)d_in[4];
    const float* sg     = (const float*)d_in[5];
    const float* su     = (const float*)d_in[6];
    const float* sd     = (const float*)d_in[7];
    float* out = (float*)d_out;

    float *Xs, *Hs, *Hr, *sgT, *suT, *sdT, *gT, *uT, *dT;
    cudaGetSymbolAddress((void**)&Xs, g_Xs);
    cudaGetSymbolAddress((void**)&Hs, g_Hs);
    cudaGetSymbolAddress((void**)&Hr, g_Hr);
    cudaGetSymbolAddress((void**)&sgT, g_sgT);
    cudaGetSymbolAddress((void**)&suT, g_suT);
    cudaGetSymbolAddress((void**)&sdT, g_sdT);
    cudaGetSymbolAddress((void**)&gT, g_gT);
    cudaGetSymbolAddress((void**)&uT, g_uT);
    cudaGetSymbolAddress((void**)&dT, g_dT);

    cudaFuncSetAttribute(k_mma, cudaFuncAttributeMaxDynamicSharedMemorySize, GEMM_SMEM);

    // routing
    k_init   <<<(PADMAX + 255) / 256, 256>>>();
    k_hist   <<<(N_TOK + 255) / 256, 256>>>(tok);
    k_scan   <<<1, 32>>>();
    k_scatter<<<(N_TOK + 255) / 256, 256>>>(tok);

    // weight transposes ([K,N] -> [N,K]) with tf32 rounding
    dim3 tb(32, 8);
    k_tr_shared<<<dim3(32, 32, 3), tb>>>(sg, su, sd);
    k_tr_gu    <<<dim3(16, 32, 16), tb>>>(gate_w, up_w);
    k_tr_down  <<<dim3(32, 16, 8), tb>>>(down_w);

    // round activations once
    k_round<<<N_TOK, 256>>>(x, Xs);

    // shared up + swiglu fused: Hs[N,1024]
    k_mma<<<dim3(16, 128), 256, GEMM_SMEM>>>(Xs, sgT, suT, Hs,
        1024, 0LL, 1024, F_SWIGLU);

    // routed up + gather + swiglu fused: Hr[pad,512]
    k_mma<<<dim3(8, PADMAX / 128), 256, GEMM_SMEM>>>(Xs, gT, uT, Hr,
        1024, (long long)512 * 1024, 512, F_SWIGLU | F_AMAP | F_EXPERT | F_LIMIT);

    // shared down: out = Hs @ sdT^T (full overwrite)
    k_mma<<<dim3(8, 128), 256, GEMM_SMEM>>>(Hs, sdT, sdT, out,
        1024, 0LL, 1024, 0);

    // routed down + scatter-add fused: out[perm[r]] += Hr @ dT[e]^T
    k_mma<<<dim3(8, PADMAX / 128), 256, GEMM_SMEM>>>(Hr, dT, dT, out,
        512, (long long)1024 * 512, 1024, F_EXPERT | F_LIMIT | F_SCATTER);
}

// round 10
// speedup vs baseline: 2.2092x; 1.6908x over previous
#include <cuda_runtime.h>
#include <cuda_fp16.h>
#include <cstdint>
#include <math.h>

// ---------------- problem constants -----------------------------------------
#define N_TOK 16384
#define H_DIM 1024
#define E_NUM 8
#define E_DIM 512
#define VOCAB 50257
#define PADMAX (N_TOK + E_NUM * 128)   // 17408

// ---------------- device state & scratch -------------------------------------
__device__ int d_counts[E_NUM];
__device__ int d_cursor[E_NUM];
__device__ int d_poff[E_NUM + 1];
__device__ int d_padded_total;
__device__ int d_perm[PADMAX];

__device__ __half g_Xh [(size_t)N_TOK * 1024];    // fp16 x
__device__ __half g_Hs [(size_t)N_TOK * 1024];    // shared hidden
__device__ __half g_Hr [(size_t)PADMAX * 512];    // routed hidden
__device__ __half g_sgT[(size_t)1024 * 1024];
__device__ __half g_suT[(size_t)1024 * 1024];
__device__ __half g_sdT[(size_t)1024 * 1024];
__device__ __half g_gT [(size_t)E_NUM * 512 * 1024];
__device__ __half g_uT [(size_t)E_NUM * 512 * 1024];
__device__ __half g_dT [(size_t)E_NUM * 1024 * 512];

// ---------------- helpers -----------------------------------------------------
__device__ __forceinline__ uint32_t smem_u32(const void* p) {
    uint32_t a;
    asm("{ .reg .u64 t; cvta.to.shared.u64 t, %1; cvt.u32.u64 %0, t; }" : "=r"(a) : "l"(p));
    return a;
}
#define CP_ASYNC16(dst, src) \
    asm volatile("cp.async.cg.shared.global [%0], [%1], 16;" :: "r"(dst), "l"(src))
#define CP_ASYNC16Z(dst, src, sz) \
    asm volatile("cp.async.cg.shared.global [%0], [%1], 16, %2;" :: "r"(dst), "l"(src), "r"(sz))
#define CP_COMMIT() asm volatile("cp.async.commit_group;")
#define CP_WAIT1()  asm volatile("cp.async.wait_group 1;")

#define LDSM4(r, addr) \
    asm volatile("ldmatrix.sync.aligned.m8n8.x4.shared.b16 {%0,%1,%2,%3}, [%4];" \
        : "=r"((r)[0]), "=r"((r)[1]), "=r"((r)[2]), "=r"((r)[3]) : "r"(addr))

__device__ __forceinline__ void mma16(float* d, const uint32_t* a, uint32_t b0, uint32_t b1) {
    asm volatile("mma.sync.aligned.m16n8k16.row.col.f32.f16.f16.f32 "
        "{%0,%1,%2,%3}, {%4,%5,%6,%7}, {%8,%9}, {%0,%1,%2,%3};"
        : "+f"(d[0]), "+f"(d[1]), "+f"(d[2]), "+f"(d[3])
        : "r"(a[0]), "r"(a[1]), "r"(a[2]), "r"(a[3]), "r"(b0), "r"(b1));
}
__device__ __forceinline__ float silu_f(float g) { return g / (1.f + __expf(-g)); }

// ---------------- routing -----------------------------------------------------
__global__ void k_init() {
    int i = blockIdx.x * blockDim.x + threadIdx.x;
    if (i < E_NUM) { d_counts[i] = 0; d_cursor[i] = 0; }
    for (int j = i; j < PADMAX; j += gridDim.x * blockDim.x) d_perm[j] = -1;
}
__device__ __forceinline__ int expert_of(int t) {
    t = t < 0 ? 0 : (t > VOCAB - 1 ? VOCAB - 1 : t);
    return t & (E_NUM - 1);
}
__global__ void k_hist(const int* __restrict__ tok) {
    int i = blockIdx.x * blockDim.x + threadIdx.x;
    if (i < N_TOK) atomicAdd(&d_counts[expert_of(tok[i])], 1);
}
__global__ void k_scan() {
    if (threadIdx.x == 0) {
        int acc = 0; d_poff[0] = 0;
        for (int e = 0; e < E_NUM; e++) { acc += (d_counts[e] + 127) & ~127; d_poff[e + 1] = acc; }
        d_padded_total = acc;
    }
}
__global__ void k_scatter(const int* __restrict__ tok) {
    int i = blockIdx.x * blockDim.x + threadIdx.x;
    if (i < N_TOK) {
        int e = expert_of(tok[i]);
        int p = atomicAdd(&d_cursor[e], 1);
        d_perm[d_poff[e] + p] = i;
    }
}

// ---------------- transposes (fp32 -> fp16) -----------------------------------
#define TR_BODY(ip, op, R, C) do { \
    __shared__ float tile[32][33]; \
    int r0 = blockIdx.y * 32, c0 = blockIdx.x * 32; \
    int tx = threadIdx.x, ty = threadIdx.y; \
    _Pragma("unroll") \
    for (int i = 0; i < 32; i += 8) tile[ty + i][tx] = (ip)[(size_t)(r0 + ty + i) * (C) + c0 + tx]; \
    __syncthreads(); \
    _Pragma("unroll") \
    for (int i = 0; i < 32; i += 8) (op)[(size_t)(c0 + ty + i) * (R) + r0 + tx] = __float2half(tile[tx][ty + i]); \
} while (0)

__global__ void k_tr_shared(const float* __restrict__ sg, const float* __restrict__ su,
                            const float* __restrict__ sd) {
    int z = blockIdx.z;
    const float* ip = z == 0 ? sg : (z == 1 ? su : sd);
    __half* op = z == 0 ? g_sgT : (z == 1 ? g_suT : g_sdT);
    TR_BODY(ip, op, 1024, 1024);
}
__global__ void k_tr_gu(const float* __restrict__ gw, const float* __restrict__ uw) {
    int z = blockIdx.z;                     // 0..15
    int e = z & 7;
    const float* ip = (z < 8 ? gw : uw) + (size_t)e * 1024 * 512;
    __half* op = (z < 8 ? g_gT : g_uT) + (size_t)e * 512 * 1024;
    TR_BODY(ip, op, 1024, 512);
}
__global__ void k_tr_down(const float* __restrict__ dw) {
    int e = blockIdx.z;                     // 0..7
    const float* ip = dw + (size_t)e * 512 * 1024;
    __half* op = g_dT + (size_t)e * 1024 * 512;
    TR_BODY(ip, op, 512, 1024);
}

__global__ void k_tohalf(const float* __restrict__ in, __half* __restrict__ out) {
    size_t i = (size_t)blockIdx.x * blockDim.x + threadIdx.x;   // N_TOK*256 float4
    float4 v = reinterpret_cast<const float4*>(in)[i];
    __half2* o = reinterpret_cast<__half2*>(out);
    o[2 * i]     = __floats2half2_rn(v.x, v.y);
    o[2 * i + 1] = __floats2half2_rn(v.z, v.w);
}

// ---------------- fused fp16 mma.sync GEMM ------------------------------------
// BM=BN=128, BK=64 (fp16), 3-stage cp.async, 256 threads, warp tile 32x64.
// Modes:
//  F_SWIGLU: B-smem rows interleave gate(even)/up(odd); CTA covers 64 true cols;
//            epilogue writes __half(silu(g)*u).
//  F_AMAP:   A rows gathered via d_perm (pads zero-filled), hoisted to prologue.
//  F_SCATTER: epilogue does float out[d_perm[r]] += acc.
#define BKG 64
#define RSF 144                     // smem row stride bytes (128 data + 16 pad)
#define STG_B (128 * RSF)           // 18432 bytes per operand per stage
#define NST 3
#define GEMM_SMEM (NST * STG_B * 2)
#define F_EXPERT  1
#define F_LIMIT   2
#define F_AMAP    4
#define F_SWIGLU  8
#define F_SCATTER 16

__global__ __launch_bounds__(256)
void k_mma(const __half* __restrict__ A, const __half* __restrict__ Bg,
           const __half* __restrict__ Bu, void* __restrict__ Cv,
           int K, long long ew_stride, int ldc, int flags)
{
    extern __shared__ __align__(128) char sm[];
    int row0 = blockIdx.y * 128;
    if ((flags & F_LIMIT) && row0 >= d_padded_total) return;
    int tid = threadIdx.x;

    const __half* bg = Bg; const __half* bu = Bu;
    if (flags & F_EXPERT) {
        int e = 0;
        #pragma unroll
        for (int i = 1; i < E_NUM; i++) if (row0 >= d_poff[i]) e = i;
        bg += (long long)e * ew_stride;
        bu += (long long)e * ew_stride;
    }
    const bool sw = (flags & F_SWIGLU) != 0;
    int col0 = blockIdx.x * (sw ? 64 : 128);

    uint32_t sA = smem_u32(sm);
    uint32_t sB = sA + NST * STG_B;

    int lane = tid & 31, wid = tid >> 5;
    int wm = wid >> 1, wn = wid & 1;            // 4 x 2 warps
    int tq = lane & 7, sel = lane >> 3;

    // ldmatrix x4 lane offsets (bytes within a stage)
    // A tiles: [rows(+0/+8), k(+0/+16B)] ; B tiles: [n(+0/+8), k(+0/+16B)]
    uint32_t aoff[2], boff[4];
    #pragma unroll
    for (int fm = 0; fm < 2; fm++)
        aoff[fm] = (uint32_t)((wm * 32 + fm * 16 + tq + (sel & 1) * 8) * RSF + (sel >> 1) * 16);
    #pragma unroll
    for (int p = 0; p < 4; p++)
        boff[p] = (uint32_t)((wn * 64 + p * 16 + tq + (sel >> 1) * 8) * RSF + (sel & 1) * 16);

    // ---- prologue: per-thread load rows resolved once ------------------------
    // 8 chunks/row (128B), 128 rows: thread handles 4 (A,B) chunks/stage.
    const __half* aP[4];
    const __half* bP[4];
    uint32_t aSz[4], dOf[4];
    #pragma unroll
    for (int p = 0; p < 4; p++) {
        int g = p * 256 + tid;
        int r = g >> 3, c = g & 7;
        dOf[p] = (uint32_t)(r * RSF + c * 16);
        int gr = row0 + r;
        int ar = (flags & F_AMAP) ? d_perm[gr] : gr;
        aP[p]  = A + ((size_t)(ar < 0 ? 0 : ar) * K + c * 8);
        aSz[p] = ar < 0 ? 0u : 16u;
        if (sw) {
            const __half* bb = (r & 1) ? bu : bg;
            bP[p] = bb + ((size_t)(col0 + (r >> 1)) * K + c * 8);
        } else {
            bP[p] = bg + ((size_t)(col0 + r) * K + c * 8);
        }
    }

    auto load_stage = [&](int st, int kt) {
        uint32_t da = sA + st * STG_B, db = sB + st * STG_B;
        int kof = kt * BKG;
        #pragma unroll
        for (int p = 0; p < 4; p++) {
            CP_ASYNC16Z(da + dOf[p], aP[p] + kof, aSz[p]);
            CP_ASYNC16 (db + dOf[p], bP[p] + kof);
        }
    };

    int KT = K / BKG;
    load_stage(0, 0); CP_COMMIT();
    load_stage(1, 1); CP_COMMIT();
    CP_WAIT1();
    __syncthreads();

    float acc[2][8][4];
    #pragma unroll
    for (int fm = 0; fm < 2; fm++)
        #pragma unroll
        for (int fn = 0; fn < 8; fn++)
            #pragma unroll
            for (int q = 0; q < 4; q++) acc[fm][fn][q] = 0.f;

    for (int kt = 0; kt < KT; kt++) {
        int st = kt % NST;
        uint32_t baseA = sA + st * STG_B, baseB = sB + st * STG_B;
        #pragma unroll
        for (int s = 0; s < 4; s++) {           // 4 x k16 = BK 64
            uint32_t a[2][4], b[4][4];
            #pragma unroll
            for (int fm = 0; fm < 2; fm++) LDSM4(a[fm], baseA + aoff[fm] + s * 32);
            #pragma unroll
            for (int p = 0; p < 4; p++)  LDSM4(b[p], baseB + boff[p] + s * 32);
            #pragma unroll
            for (int fm = 0; fm < 2; fm++)
                #pragma unroll
                for (int fn = 0; fn < 8; fn++) {
                    const uint32_t* bp = b[fn >> 1];
                    if (fn & 1) mma16(acc[fm][fn], a[fm], bp[2], bp[3]);
                    else        mma16(acc[fm][fn], a[fm], bp[0], bp[1]);
                }
        }
        if (kt + 2 < KT) load_stage((kt + 2) % NST, kt + 2);
        CP_COMMIT();
        CP_WAIT1();
        __syncthreads();
    }

    int gid = lane >> 2, tig = lane & 3;
    if (sw) {
        __half* Ch = (__half*)Cv;
        // acc pair (even,odd B-row) = (gate, up) of true col tc
        #pragma unroll
        for (int fm = 0; fm < 2; fm++) {
            int r = row0 + wm * 32 + fm * 16 + gid;
            #pragma unroll
            for (int fn = 0; fn < 8; fn++) {
                int tc = col0 + wn * 32 + fn * 4 + tig;
                float* d = acc[fm][fn];
                Ch[(size_t)r * ldc + tc]       = __float2half(silu_f(d[0]) * d[1]);
                Ch[(size_t)(r + 8) * ldc + tc] = __float2half(silu_f(d[2]) * d[3]);
            }
        }
    } else if (flags & F_SCATTER) {
        float* Cf = (float*)Cv;
        #pragma unroll
        for (int fm = 0; fm < 2; fm++) {
            #pragma unroll
            for (int q = 0; q < 2; q++) {
                int r = row0 + wm * 32 + fm * 16 + gid + q * 8;
                int t = d_perm[r];
                if (t < 0) continue;
                #pragma unroll
                for (int fn = 0; fn < 8; fn++) {
                    int c = col0 + wn * 64 + fn * 8 + 2 * tig;
                    float2* p = reinterpret_cast<float2*>(&Cf[(size_t)t * ldc + c]);
                    float2 v = *p;
                    v.x += acc[fm][fn][q * 2];
                    v.y += acc[fm][fn][q * 2 + 1];
                    *p = v;
                }
            }
        }
    } else {
        float* Cf = (float*)Cv;
        #pragma unroll
        for (int fm = 0; fm < 2; fm++) {
            #pragma unroll
            for (int fn = 0; fn < 8; fn++) {
                int r = row0 + wm * 32 + fm * 16 + gid;
                int c = col0 + wn * 64 + fn * 8 + 2 * tig;
                *reinterpret_cast<float2*>(&Cf[(size_t)r * ldc + c]) =
                    make_float2(acc[fm][fn][0], acc[fm][fn][1]);
                *reinterpret_cast<float2*>(&Cf[(size_t)(r + 8) * ldc + c]) =
                    make_float2(acc[fm][fn][2], acc[fm][fn][3]);
            }
        }
    }
}

// ---------------- launch ------------------------------------------------------
extern "C" void kernel_launch(void* const* d_in, const int* in_sizes, int n_in,
                              void* d_out, int out_size) {
    const float* x      = (const float*)d_in[0];
    const int*   tok    = (const int*)  d_in[1];
    const float* gate_w = (const float*)d_in[2];
    const float* up_w   = (const float*)d_in[3];
    const float* down_w = (const float*)d_in[4];
    const float* sg     = (const float*)d_in[5];
    const float* su     = (const float*)d_in[6];
    const float* sd     = (const float*)d_in[7];
    float* out = (float*)d_out;

    __half *Xh, *Hs, *Hr, *sgT, *suT, *sdT, *gT, *uT, *dT;
    cudaGetSymbolAddress((void**)&Xh, g_Xh);
    cudaGetSymbolAddress((void**)&Hs, g_Hs);
    cudaGetSymbolAddress((void**)&Hr, g_Hr);
    cudaGetSymbolAddress((void**)&sgT, g_sgT);
    cudaGetSymbolAddress((void**)&suT, g_suT);
    cudaGetSymbolAddress((void**)&sdT, g_sdT);
    cudaGetSymbolAddress((void**)&gT, g_gT);
    cudaGetSymbolAddress((void**)&uT, g_uT);
    cudaGetSymbolAddress((void**)&dT, g_dT);

    cudaFuncSetAttribute(k_mma, cudaFuncAttributeMaxDynamicSharedMemorySize, GEMM_SMEM);

    // routing
    k_init   <<<(PADMAX + 255) / 256, 256>>>();
    k_hist   <<<(N_TOK + 255) / 256, 256>>>(tok);
    k_scan   <<<1, 32>>>();
    k_scatter<<<(N_TOK + 255) / 256, 256>>>(tok);

    // weight transposes ([K,N] -> [N,K]) fp32 -> fp16
    dim3 tb(32, 8);
    k_tr_shared<<<dim3(32, 32, 3), tb>>>(sg, su, sd);
    k_tr_gu    <<<dim3(16, 32, 16), tb>>>(gate_w, up_w);
    k_tr_down  <<<dim3(32, 16, 8), tb>>>(down_w);

    // x -> fp16
    k_tohalf<<<N_TOK, 256>>>(x, Xh);

    // shared up + swiglu fused: Hs[N,1024] (fp16)
    k_mma<<<dim3(16, 128), 256, GEMM_SMEM>>>(Xh, sgT, suT, Hs,
        1024, 0LL, 1024, F_SWIGLU);

    // routed up + gather + swiglu fused: Hr[pad,512] (fp16)
    k_mma<<<dim3(8, PADMAX / 128), 256, GEMM_SMEM>>>(Xh, gT, uT, Hr,
        1024, (long long)512 * 1024, 512, F_SWIGLU | F_AMAP | F_EXPERT | F_LIMIT);

    // shared down: out = Hs @ sdT^T (fp32 overwrite)
    k_mma<<<dim3(8, 128), 256, GEMM_SMEM>>>(Hs, sdT, sdT, out,
        1024, 0LL, 1024, 0);

    // routed down + scatter-add fused: out[perm[r]] += Hr @ dT[e]^T
    k_mma<<<dim3(8, PADMAX / 128), 256, GEMM_SMEM>>>(Hr, dT, dT, out,
        512, (long long)1024 * 512, 1024, F_EXPERT | F_LIMIT | F_SCATTER);
}

// round 11
// speedup vs baseline: 2.4323x; 1.1010x over previous
#include <cuda_runtime.h>
#include <cuda_fp16.h>
#include <cstdint>
#include <math.h>

// ---------------- problem constants -----------------------------------------
#define N_TOK 16384
#define H_DIM 1024
#define E_NUM 8
#define E_DIM 512
#define VOCAB 50257
#define PADMAX (N_TOK + E_NUM * 128)   // 17408

// ---------------- device state & scratch -------------------------------------
__device__ int d_counts[E_NUM];
__device__ int d_cursor[E_NUM];
__device__ int d_poff[E_NUM + 1];
__device__ int d_padded_total;
__device__ int d_perm[PADMAX];

__device__ __half g_Xh [(size_t)N_TOK * 1024];    // fp16 x
__device__ __half g_Hs [(size_t)N_TOK * 1024];    // shared hidden
__device__ __half g_Hr [(size_t)PADMAX * 512];    // routed hidden
__device__ __half g_sgT[(size_t)1024 * 1024];
__device__ __half g_suT[(size_t)1024 * 1024];
__device__ __half g_sdT[(size_t)1024 * 1024];
__device__ __half g_gT [(size_t)E_NUM * 512 * 1024];
__device__ __half g_uT [(size_t)E_NUM * 512 * 1024];
__device__ __half g_dT [(size_t)E_NUM * 1024 * 512];

// ---------------- helpers -----------------------------------------------------
__device__ __forceinline__ uint32_t smem_u32(const void* p) {
    uint32_t a;
    asm("{ .reg .u64 t; cvta.to.shared.u64 t, %1; cvt.u32.u64 %0, t; }" : "=r"(a) : "l"(p));
    return a;
}
#define CP_ASYNC16(dst, src) \
    asm volatile("cp.async.cg.shared.global [%0], [%1], 16;" :: "r"(dst), "l"(src))
#define CP_ASYNC16Z(dst, src, sz) \
    asm volatile("cp.async.cg.shared.global [%0], [%1], 16, %2;" :: "r"(dst), "l"(src), "r"(sz))
#define CP_COMMIT() asm volatile("cp.async.commit_group;")
#define CP_WAIT1()  asm volatile("cp.async.wait_group 1;")

#define LDSM4(r, addr) \
    asm volatile("ldmatrix.sync.aligned.m8n8.x4.shared.b16 {%0,%1,%2,%3}, [%4];" \
        : "=r"((r)[0]), "=r"((r)[1]), "=r"((r)[2]), "=r"((r)[3]) : "r"(addr))

__device__ __forceinline__ void mma16(float* d, const uint32_t* a, uint32_t b0, uint32_t b1) {
    asm volatile("mma.sync.aligned.m16n8k16.row.col.f32.f16.f16.f32 "
        "{%0,%1,%2,%3}, {%4,%5,%6,%7}, {%8,%9}, {%0,%1,%2,%3};"
        : "+f"(d[0]), "+f"(d[1]), "+f"(d[2]), "+f"(d[3])
        : "r"(a[0]), "r"(a[1]), "r"(a[2]), "r"(a[3]), "r"(b0), "r"(b1));
}
__device__ __forceinline__ float silu_f(float g) { return g / (1.f + __expf(-g)); }

// ---------------- routing -----------------------------------------------------
__global__ void k_init() {
    int i = blockIdx.x * blockDim.x + threadIdx.x;
    if (i < E_NUM) { d_counts[i] = 0; d_cursor[i] = 0; }
    for (int j = i; j < PADMAX; j += gridDim.x * blockDim.x) d_perm[j] = -1;
}
__device__ __forceinline__ int expert_of(int t) {
    t = t < 0 ? 0 : (t > VOCAB - 1 ? VOCAB - 1 : t);
    return t & (E_NUM - 1);
}
__global__ void k_hist(const int* __restrict__ tok) {
    int i = blockIdx.x * blockDim.x + threadIdx.x;
    if (i < N_TOK) atomicAdd(&d_counts[expert_of(tok[i])], 1);
}
__global__ void k_scan() {
    if (threadIdx.x == 0) {
        int acc = 0; d_poff[0] = 0;
        for (int e = 0; e < E_NUM; e++) { acc += (d_counts[e] + 127) & ~127; d_poff[e + 1] = acc; }
        d_padded_total = acc;
    }
}
__global__ void k_scatter(const int* __restrict__ tok) {
    int i = blockIdx.x * blockDim.x + threadIdx.x;
    if (i < N_TOK) {
        int e = expert_of(tok[i]);
        int p = atomicAdd(&d_cursor[e], 1);
        d_perm[d_poff[e] + p] = i;
    }
}

// ---------------- transposes (fp32 -> fp16) -----------------------------------
#define TR_BODY(ip, op, R, C) do { \
    __shared__ float tile[32][33]; \
    int r0 = blockIdx.y * 32, c0 = blockIdx.x * 32; \
    int tx = threadIdx.x, ty = threadIdx.y; \
    _Pragma("unroll") \
    for (int i = 0; i < 32; i += 8) tile[ty + i][tx] = (ip)[(size_t)(r0 + ty + i) * (C) + c0 + tx]; \
    __syncthreads(); \
    _Pragma("unroll") \
    for (int i = 0; i < 32; i += 8) (op)[(size_t)(c0 + ty + i) * (R) + r0 + tx] = __float2half(tile[tx][ty + i]); \
} while (0)

__global__ void k_tr_shared(const float* __restrict__ sg, const float* __restrict__ su,
                            const float* __restrict__ sd) {
    int z = blockIdx.z;
    const float* ip = z == 0 ? sg : (z == 1 ? su : sd);
    __half* op = z == 0 ? g_sgT : (z == 1 ? g_suT : g_sdT);
    TR_BODY(ip, op, 1024, 1024);
}
__global__ void k_tr_gu(const float* __restrict__ gw, const float* __restrict__ uw) {
    int z = blockIdx.z;                     // 0..15
    int e = z & 7;
    const float* ip = (z < 8 ? gw : uw) + (size_t)e * 1024 * 512;
    __half* op = (z < 8 ? g_gT : g_uT) + (size_t)e * 512 * 1024;
    TR_BODY(ip, op, 1024, 512);
}
__global__ void k_tr_down(const float* __restrict__ dw) {
    int e = blockIdx.z;                     // 0..7
    const float* ip = dw + (size_t)e * 512 * 1024;
    __half* op = g_dT + (size_t)e * 1024 * 512;
    TR_BODY(ip, op, 512, 1024);
}

__global__ void k_tohalf(const float* __restrict__ in, __half* __restrict__ out) {
    size_t i = (size_t)blockIdx.x * blockDim.x + threadIdx.x;   // N_TOK*256 float4
    float4 v = reinterpret_cast<const float4*>(in)[i];
    __half2* o = reinterpret_cast<__half2*>(out);
    o[2 * i]     = __floats2half2_rn(v.x, v.y);
    o[2 * i + 1] = __floats2half2_rn(v.z, v.w);
}

// ---------------- GEMM common -------------------------------------------------
#define BKG 64
#define RSF 144                     // smem row stride bytes (128 data + 16 pad)
#define STG_B (128 * RSF)           // 18432 bytes per operand per stage
#define NST 3
#define GEMM_SMEM (NST * STG_B * 2)
#define F_EXPERT  1
#define F_LIMIT   2
#define F_AMAP    4

// mainloop body shared by both kernels (KT iterations, prefetch depth 2)
#define MAINLOOP(KT_) \
    for (int kt = 0; kt < (KT_); kt++) { \
        int st = kt % NST; \
        uint32_t baseA = sA + st * STG_B, baseB = sB + st * STG_B; \
        _Pragma("unroll") \
        for (int s = 0; s < 4; s++) { \
            uint32_t a[2][4], b[4][4]; \
            _Pragma("unroll") \
            for (int fm = 0; fm < 2; fm++) LDSM4(a[fm], baseA + aoff[fm] + s * 32); \
            _Pragma("unroll") \
            for (int p = 0; p < 4; p++)  LDSM4(b[p], baseB + boff[p] + s * 32); \
            _Pragma("unroll") \
            for (int fm = 0; fm < 2; fm++) \
                _Pragma("unroll") \
                for (int fn = 0; fn < 8; fn++) { \
                    const uint32_t* bp = b[fn >> 1]; \
                    if (fn & 1) mma16(acc[fm][fn], a[fm], bp[2], bp[3]); \
                    else        mma16(acc[fm][fn], a[fm], bp[0], bp[1]); \
                } \
        } \
        if (kt + 2 < (KT_)) load_stage((kt + 2) % NST, kt + 2); \
        CP_COMMIT(); \
        CP_WAIT1(); \
        __syncthreads(); \
    }

#define FRAG_SETUP \
    int lane = tid & 31, wid = tid >> 5; \
    int wm = wid >> 1, wn = wid & 1; \
    int tq = lane & 7, sel = lane >> 3; \
    uint32_t aoff[2], boff[4]; \
    _Pragma("unroll") \
    for (int fm = 0; fm < 2; fm++) \
        aoff[fm] = (uint32_t)((wm * 32 + fm * 16 + tq + (sel & 1) * 8) * RSF + (sel >> 1) * 16); \
    _Pragma("unroll") \
    for (int p = 0; p < 4; p++) \
        boff[p] = (uint32_t)((wn * 64 + p * 16 + tq + (sel >> 1) * 8) * RSF + (sel & 1) * 16); \
    float acc[2][8][4]; \
    _Pragma("unroll") \
    for (int fm = 0; fm < 2; fm++) \
        _Pragma("unroll") \
        for (int fn = 0; fn < 8; fn++) \
            _Pragma("unroll") \
            for (int q = 0; q < 4; q++) acc[fm][fn][q] = 0.f;

// ---------------- up-projection GEMM + swiglu (8-row-group interleave) --------
// B smem rows: group g=r>>3 (0..15); g even -> gate, g odd -> up, of true cols
// col0 + (g>>1)*8 + (r&7). CTA covers 64 true cols. Epilogue: half2 stores.
__global__ __launch_bounds__(256)
void k_up(const __half* __restrict__ A, const __half* __restrict__ Bg,
          const __half* __restrict__ Bu, __half* __restrict__ C,
          int K, long long ew_stride, int ldc, int flags)
{
    extern __shared__ __align__(128) char sm[];
    int row0 = blockIdx.y * 128;
    if ((flags & F_LIMIT) && row0 >= d_padded_total) return;
    int tid = threadIdx.x;

    const __half* bg = Bg; const __half* bu = Bu;
    if (flags & F_EXPERT) {
        int e = 0;
        #pragma unroll
        for (int i = 1; i < E_NUM; i++) if (row0 >= d_poff[i]) e = i;
        bg += (long long)e * ew_stride;
        bu += (long long)e * ew_stride;
    }
    int col0 = blockIdx.x * 64;

    uint32_t sA = smem_u32(sm);
    uint32_t sB = sA + NST * STG_B;
    FRAG_SETUP;

    const __half* aP[4];
    const __half* bP[4];
    uint32_t aSz[4], dOf[4];
    #pragma unroll
    for (int p = 0; p < 4; p++) {
        int g = p * 256 + tid;
        int r = g >> 3, c = g & 7;
        dOf[p] = (uint32_t)(r * RSF + c * 16);
        int gr = row0 + r;
        int ar = (flags & F_AMAP) ? d_perm[gr] : gr;
        aP[p]  = A + ((size_t)(ar < 0 ? 0 : ar) * K + c * 8);
        aSz[p] = ar < 0 ? 0u : 16u;
        int grp = r >> 3;
        const __half* bb = (grp & 1) ? bu : bg;
        int n = col0 + (grp >> 1) * 8 + (r & 7);
        bP[p] = bb + ((size_t)n * K + c * 8);
    }

    auto load_stage = [&](int st, int kt) {
        uint32_t da = sA + st * STG_B, db = sB + st * STG_B;
        int kof = kt * BKG;
        #pragma unroll
        for (int p = 0; p < 4; p++) {
            CP_ASYNC16Z(da + dOf[p], aP[p] + kof, aSz[p]);
            CP_ASYNC16 (db + dOf[p], bP[p] + kof);
        }
    };

    int KT = K / BKG;
    load_stage(0, 0); CP_COMMIT();
    load_stage(1, 1); CP_COMMIT();
    CP_WAIT1();
    __syncthreads();

    MAINLOOP(KT);

    // epilogue: fn even = gate, fn odd = up of same cols; pack half2
    int gid = lane >> 2, tig = lane & 3;
    #pragma unroll
    for (int fm = 0; fm < 2; fm++) {
        int r = row0 + wm * 32 + fm * 16 + gid;
        #pragma unroll
        for (int j = 0; j < 4; j++) {
            float* dg = acc[fm][2 * j];
            float* du = acc[fm][2 * j + 1];
            int tc = col0 + (wn * 4 + j) * 8 + 2 * tig;
            __half2 h0 = __floats2half2_rn(silu_f(dg[0]) * du[0], silu_f(dg[1]) * du[1]);
            __half2 h1 = __floats2half2_rn(silu_f(dg[2]) * du[2], silu_f(dg[3]) * du[3]);
            *reinterpret_cast<__half2*>(&C[(size_t)r * ldc + tc]) = h0;
            *reinterpret_cast<__half2*>(&C[(size_t)(r + 8) * ldc + tc]) = h1;
        }
    }
}

// ---------------- merged down-projection GEMM ---------------------------------
// out[perm[r]] = Hs[perm[r]] @ sdT^T + Hr[r] @ dT[e]^T   (K = 1024 + 512)
// Pure scatter-WRITE epilogue (perm bijective over tokens -> full coverage).
#define KT1 (1024 / BKG)   // 16
#define KT2 (512 / BKG)    // 8
#define KTD (KT1 + KT2)    // 24

__global__ __launch_bounds__(256)
void k_down(const __half* __restrict__ Hs, const __half* __restrict__ Hr,
            const __half* __restrict__ B1, const __half* __restrict__ B2e,
            float* __restrict__ out)
{
    extern __shared__ __align__(128) char sm[];
    int row0 = blockIdx.y * 128;
    if (row0 >= d_padded_total) return;
    int tid = threadIdx.x;

    int e = 0;
    #pragma unroll
    for (int i = 1; i < E_NUM; i++) if (row0 >= d_poff[i]) e = i;
    const __half* B2 = B2e + (long long)e * 1024 * 512;
    int col0 = blockIdx.x * 128;

    uint32_t sA = smem_u32(sm);
    uint32_t sB = sA + NST * STG_B;
    FRAG_SETUP;

    const __half* a1P[4]; const __half* a2P[4];
    const __half* b1P[4]; const __half* b2P[4];
    uint32_t aSz[4], dOf[4];
    #pragma unroll
    for (int p = 0; p < 4; p++) {
        int g = p * 256 + tid;
        int r = g >> 3, c = g & 7;
        dOf[p] = (uint32_t)(r * RSF + c * 16);
        int gr = row0 + r;
        int ar = d_perm[gr];
        a1P[p] = Hs + ((size_t)(ar < 0 ? 0 : ar) * 1024 + c * 8);
        a2P[p] = Hr + ((size_t)gr * 512 + c * 8);
        aSz[p] = ar < 0 ? 0u : 16u;
        int n = col0 + r;
        b1P[p] = B1 + ((size_t)n * 1024 + c * 8);
        b2P[p] = B2 + ((size_t)n * 512 + c * 8);
    }

    auto load_stage = [&](int st, int kt) {
        uint32_t da = sA + st * STG_B, db = sB + st * STG_B;
        if (kt < KT1) {
            int kof = kt * BKG;
            #pragma unroll
            for (int p = 0; p < 4; p++) {
                CP_ASYNC16Z(da + dOf[p], a1P[p] + kof, aSz[p]);
                CP_ASYNC16 (db + dOf[p], b1P[p] + kof);
            }
        } else {
            int kof = (kt - KT1) * BKG;
            #pragma unroll
            for (int p = 0; p < 4; p++) {
                CP_ASYNC16Z(da + dOf[p], a2P[p] + kof, aSz[p]);
                CP_ASYNC16 (db + dOf[p], b2P[p] + kof);
            }
        }
    };

    load_stage(0, 0); CP_COMMIT();
    load_stage(1, 1); CP_COMMIT();
    CP_WAIT1();
    __syncthreads();

    MAINLOOP(KTD);

    // scatter-write epilogue (no read of out)
    int gid = lane >> 2, tig = lane & 3;
    #pragma unroll
    for (int fm = 0; fm < 2; fm++) {
        #pragma unroll
        for (int q = 0; q < 2; q++) {
            int r = row0 + wm * 32 + fm * 16 + gid + q * 8;
            int t = d_perm[r];
            if (t < 0) continue;
            #pragma unroll
            for (int fn = 0; fn < 8; fn++) {
                int c = col0 + wn * 64 + fn * 8 + 2 * tig;
                *reinterpret_cast<float2*>(&out[(size_t)t * 1024 + c]) =
                    make_float2(acc[fm][fn][q * 2], acc[fm][fn][q * 2 + 1]);
            }
        }
    }
}

// ---------------- launch ------------------------------------------------------
extern "C" void kernel_launch(void* const* d_in, const int* in_sizes, int n_in,
                              void* d_out, int out_size) {
    const float* x      = (const float*)d_in[0];
    const int*   tok    = (const int*)  d_in[1];
    const float* gate_w = (const float*)d_in[2];
    const float* up_w   = (const float*)d_in[3];
    const float* down_w = (const float*)d_in[4];
    const float* sg     = (const float*)d_in[5];
    const float* su     = (const float*)d_in[6];
    const float* sd     = (const float*)d_in[7];
    float* out = (float*)d_out;

    __half *Xh, *Hs, *Hr, *sgT, *suT, *sdT, *gT, *uT, *dT;
    cudaGetSymbolAddress((void**)&Xh, g_Xh);
    cudaGetSymbolAddress((void**)&Hs, g_Hs);
    cudaGetSymbolAddress((void**)&Hr, g_Hr);
    cudaGetSymbolAddress((void**)&sgT, g_sgT);
    cudaGetSymbolAddress((void**)&suT, g_suT);
    cudaGetSymbolAddress((void**)&sdT, g_sdT);
    cudaGetSymbolAddress((void**)&gT, g_gT);
    cudaGetSymbolAddress((void**)&uT, g_uT);
    cudaGetSymbolAddress((void**)&dT, g_dT);

    cudaFuncSetAttribute(k_up,   cudaFuncAttributeMaxDynamicSharedMemorySize, GEMM_SMEM);
    cudaFuncSetAttribute(k_down, cudaFuncAttributeMaxDynamicSharedMemorySize, GEMM_SMEM);

    // routing
    k_init   <<<(PADMAX + 255) / 256, 256>>>();
    k_hist   <<<(N_TOK + 255) / 256, 256>>>(tok);
    k_scan   <<<1, 32>>>();
    k_scatter<<<(N_TOK + 255) / 256, 256>>>(tok);

    // weight transposes ([K,N] -> [N,K]) fp32 -> fp16
    dim3 tb(32, 8);
    k_tr_shared<<<dim3(32, 32, 3), tb>>>(sg, su, sd);
    k_tr_gu    <<<dim3(16, 32, 16), tb>>>(gate_w, up_w);
    k_tr_down  <<<dim3(32, 16, 8), tb>>>(down_w);

    // x -> fp16
    k_tohalf<<<N_TOK, 256>>>(x, Xh);

    // shared up + swiglu fused: Hs[N,1024]
    k_up<<<dim3(16, 128), 256, GEMM_SMEM>>>(Xh, sgT, suT, Hs,
        1024, 0LL, 1024, 0);

    // routed up + gather + swiglu fused: Hr[pad,512]
    k_up<<<dim3(8, PADMAX / 128), 256, GEMM_SMEM>>>(Xh, gT, uT, Hr,
        1024, (long long)512 * 1024, 512, F_AMAP | F_EXPERT | F_LIMIT);

    // merged down: out[perm[r]] = Hs[perm[r]]@sdT + Hr[r]@dT[e]  (scatter write)
    k_down<<<dim3(8, PADMAX / 128), 256, GEMM_SMEM>>>(Hs, Hr, sdT, dT, out);
}